// round 8
// baseline (speedup 1.0000x reference)
#include <cuda_runtime.h>
#include <cuda_bf16.h>
#include <math.h>
#include <stdint.h>

#define BATCH 16
#define CCH   2048
#define HWD   1024
#define DD    256
#define BN_RS 0.9999950000374997f   // 1/sqrt(1 + 1e-5)

// ---------------- scratch (device globals; no allocation) ----------------
__device__ __align__(16) float d_Yv [BATCH * DD  * CCH];   // psi(v2l) fp32
__device__ __align__(16) float d_Zl [BATCH * CCH * DD ];   // psi(l2v)^T fp32
__device__ __align__(16) float d_G  [BATCH * DD  * DD ];   // gram fp32
__device__ float d_invr[BATCH * DD];

// bf16 hi/lo split storage (weights + intermediates only; big inputs stay fp32)
__device__ __align__(16) __nv_bfloat16 g_wvh[DD*HWD], g_wvl[DD*HWD];
__device__ __align__(16) __nv_bfloat16 g_wlh[DD*HWD], g_wll[DD*HWD];
__device__ __align__(16) __nv_bfloat16 g_Eh[BATCH*DD*HWD], g_El[BATCH*DD*HWD];
__device__ __align__(16) __nv_bfloat16 g_Oh[BATCH*DD*HWD], g_Ol[BATCH*DD*HWD];
__device__ __align__(16) __nv_bfloat16 g_Zh[BATCH*CCH*DD], g_Zlo[BATCH*CCH*DD];
__device__ __align__(16) __nv_bfloat16 g_lath[BATCH*DD*HWD], g_latl[BATCH*DD*HWD];
__device__ __align__(16) __nv_bfloat16 g_latTh[BATCH*HWD*DD], g_latTl[BATCH*HWD*DD];
__device__ __align__(16) __nv_bfloat16 g_Gh[BATCH*DD*DD], g_Gl[BATCH*DD*DD];
__device__ __align__(16) __nv_bfloat16 g_l2Th[BATCH*HWD*DD], g_l2Tl[BATCH*HWD*DD];

// ---------------- helpers ----------------
__device__ __forceinline__ uint32_t cvta_s(const void* p){
    return (uint32_t)__cvta_generic_to_shared(p);
}
__device__ __forceinline__ void cpa16(uint32_t d, const void* s){
    asm volatile("cp.async.cg.shared.global [%0], [%1], 16;" :: "r"(d), "l"(s));
}
#define CP_COMMIT() asm volatile("cp.async.commit_group;")
#define CP_WAIT1()  asm volatile("cp.async.wait_group 1;")
#define CP_WAIT2()  asm volatile("cp.async.wait_group 2;")

#define LDSM4(R, addr) \
    asm volatile("ldmatrix.sync.aligned.m8n8.x4.shared.b16 {%0,%1,%2,%3}, [%4];" \
        : "=r"((R)[0]), "=r"((R)[1]), "=r"((R)[2]), "=r"((R)[3]) : "r"(addr))

#define MMA16816(d, A, b0, b1) \
    asm volatile("mma.sync.aligned.m16n8k16.row.col.f32.bf16.bf16.f32 " \
        "{%0,%1,%2,%3}, {%4,%5,%6,%7}, {%8,%9}, {%0,%1,%2,%3};" \
        : "+f"((d)[0]), "+f"((d)[1]), "+f"((d)[2]), "+f"((d)[3]) \
        : "r"((A)[0]), "r"((A)[1]), "r"((A)[2]), "r"((A)[3]), "r"(b0), "r"(b1))

// split float4 -> packed bf16x2 hi (trunc) / lo (rn of exact residual)
__device__ __forceinline__ void split16(float4 v, uint2& hi, uint2& lo){
    uint32_t ux = __float_as_uint(v.x), uy = __float_as_uint(v.y);
    uint32_t uz = __float_as_uint(v.z), uw = __float_as_uint(v.w);
    hi.x = __byte_perm(ux, uy, 0x7632);
    hi.y = __byte_perm(uz, uw, 0x7632);
    float lx = v.x - __uint_as_float(ux & 0xFFFF0000u);
    float ly = v.y - __uint_as_float(uy & 0xFFFF0000u);
    float lz = v.z - __uint_as_float(uz & 0xFFFF0000u);
    float lw = v.w - __uint_as_float(uw & 0xFFFF0000u);
    __nv_bfloat162 l01 = __floats2bfloat162_rn(lx, ly);
    __nv_bfloat162 l23 = __floats2bfloat162_rn(lz, lw);
    lo.x = *(uint32_t*)&l01;
    lo.y = *(uint32_t*)&l23;
}
__device__ __forceinline__ uint32_t pack_hi(float x, float y){
    return __byte_perm(__float_as_uint(x), __float_as_uint(y), 0x7632);
}
__device__ __forceinline__ uint32_t pack_lo(float x, float y){
    float lx = x - __uint_as_float(__float_as_uint(x) & 0xFFFF0000u);
    float ly = y - __uint_as_float(__float_as_uint(y) & 0xFFFF0000u);
    __nv_bfloat162 p = __floats2bfloat162_rn(lx, ly);
    return *(uint32_t*)&p;
}

// ---------------- bf16 hi/lo NT GEMM, cp.async pipelined -------------------
// D[m,n] = sum_p sum_k A_p[m,k]*B_p[n,k], 3 bf16 passes (hh + hl + lh)
// CVT: 0 = both operands pre-split bf16; 1 = A is fp32 (convert in-kernel);
//      2 = B is fp32 (convert in-kernel). Fp32 source = F0/F1.
struct GArgs {
    const __nv_bfloat16 *A0h, *A0l, *B0h, *B0l;
    const __nv_bfloat16 *A1h, *A1l, *B1h, *B1l;
    const float *F0, *F1;
    void *C, *C2;                   // EPI 0/1/2: C=float*; EPI 3: C=hi bf16*, C2=lo bf16*
    const float *gs, *bs;
    long sA, sB, sC;
    int lda, ldb, ldc, K;
};

// BM=128, BN=128, K-chunk 32. Pre-split tile: 16KB (hi 8K + lo 8K), rows 64B,
// swizzle quarter q = ch ^ ((row>>1)&3). Fp32 tile: 16KB linear.
template<int EPI, int NP, int CVT>
__global__ void __launch_bounds__(256, 1) mma_gemm(GArgs a)
{
    constexpr int PSTG = (CVT == 0) ? 32768 : 16384;  // pre-split ring stage bytes
    constexpr uint32_t F32O = 4u * 16384u;            // fp32 ring offset (CVT only)
    constexpr uint32_t CVBO = F32O + 4u * 16384u;     // bf16 dbuf offset (CVT only)

    extern __shared__ __align__(128) char smem[];
    const int tid = threadIdx.x, w = tid >> 5, lane = tid & 31;
    const int bn0 = blockIdx.x << 7, bm0 = blockIdx.y << 7, b = blockIdx.z;
    const int KS = a.K >> 5;
    const int NS = KS * NP;
    const uint32_t sbase = cvta_s(smem);
    const int wm = w >> 2, wn = w & 3;

    // cp.async mapping (pre-split operand)
    const int r0 = tid >> 2, ch = tid & 3;
    const uint32_t q16 = (uint32_t)((ch ^ ((r0 >> 1) & 3)) * 16);

    auto issue = [&](int s){
        if (s >= NS) return;
        int p = (NP == 2 && s >= KS) ? 1 : 0;
        long k0 = (long)(s - p * KS) * 32;
        // pre-split A
        if (CVT != 1){
            const __nv_bfloat16* Ah = (p ? a.A1h : a.A0h) + (long)b * a.sA + (long)bm0 * a.lda + k0;
            const __nv_bfloat16* Al = (p ? a.A1l : a.A0l) + (long)b * a.sA + (long)bm0 * a.lda + k0;
            uint32_t dst = sbase + (uint32_t)(s & 3) * PSTG + (uint32_t)r0 * 64u + q16;
            const __nv_bfloat16* ap = Ah + (long)r0 * a.lda + ch * 8;
            const __nv_bfloat16* lp = Al + (long)r0 * a.lda + ch * 8;
            cpa16(dst,         ap);
            cpa16(dst + 4096,  ap + (long)64 * a.lda);
            cpa16(dst + 8192,        lp);
            cpa16(dst + 8192 + 4096, lp + (long)64 * a.lda);
        }
        // pre-split B
        if (CVT != 2){
            const __nv_bfloat16* Bh = (p ? a.B1h : a.B0h) + (long)b * a.sB + (long)bn0 * a.ldb + k0;
            const __nv_bfloat16* Bl = (p ? a.B1l : a.B0l) + (long)b * a.sB + (long)bn0 * a.ldb + k0;
            uint32_t dst = sbase + (uint32_t)(s & 3) * PSTG + (uint32_t)(CVT == 0 ? 16384 : 0)
                         + (uint32_t)r0 * 64u + q16;
            const __nv_bfloat16* bp = Bh + (long)r0 * a.ldb + ch * 8;
            const __nv_bfloat16* lp = Bl + (long)r0 * a.ldb + ch * 8;
            cpa16(dst,         bp);
            cpa16(dst + 4096,  bp + (long)64 * a.ldb);
            cpa16(dst + 8192,        lp);
            cpa16(dst + 8192 + 4096, lp + (long)64 * a.ldb);
        }
        // fp32 operand into linear ring
        if (CVT != 0){
            const int ldf  = (CVT == 1) ? a.lda : a.ldb;
            const long sF  = (CVT == 1) ? a.sA  : a.sB;
            const int off0 = (CVT == 1) ? bm0   : bn0;
            const float* Fp = (p ? a.F1 : a.F0) + (long)b * sF + (long)off0 * ldf + k0;
            uint32_t fd = sbase + F32O + (uint32_t)(s & 3) * 16384u;
            #pragma unroll
            for (int jj = 0; jj < 4; jj++){
                int f = tid + jj * 256;
                cpa16(fd + (uint32_t)f * 16u, Fp + (long)(f >> 3) * ldf + (f & 7) * 4);
            }
        }
    };

    auto convert = [&](int i){
        if (CVT == 0 || i >= NS) return;
        char* fb = smem + F32O + (i & 3) * 16384;
        char* db = smem + CVBO + (i & 1) * 16384;
        #pragma unroll
        for (int jj = 0; jj < 4; jj++){
            int f = tid + jj * 256;
            float4 v = *(const float4*)(fb + f * 16);
            uint2 hi, lo;
            split16(v, hi, lo);
            int row = f >> 3, c4 = f & 7;
            uint32_t off = (uint32_t)row * 64u
                         + (uint32_t)(((c4 >> 1) ^ ((row >> 1) & 3)) * 16) + (uint32_t)(c4 & 1) * 8u;
            *(uint2*)(db + off)        = hi;
            *(uint2*)(db + 8192 + off) = lo;
        }
    };

    float acc[4][4][4];
    #pragma unroll
    for (int i = 0; i < 4; i++)
        #pragma unroll
        for (int j = 0; j < 4; j++)
            #pragma unroll
            for (int t = 0; t < 4; t++) acc[i][j][t] = 0.0f;

    // ldmatrix addressing
    const int aRow = wm * 64 + (lane & 15);
    const uint32_t lqA = (uint32_t)(((lane & 15) >> 1) & 3);
    const uint32_t aC0 = (uint32_t)(lane >> 4);
    const int bRow = wn * 32 + (lane & 7) + ((lane >> 4) & 1) * 8;
    const uint32_t lqB = (uint32_t)(((lane & 7) >> 1) & 3);
    const uint32_t bC0 = (uint32_t)((lane >> 3) & 1);

    // prologue
    issue(0); CP_COMMIT();
    issue(1); CP_COMMIT();
    issue(2); CP_COMMIT();
    if (CVT != 0){
        CP_WAIT2();
        __syncthreads();
        convert(0);
    }

    for (int i = 0; i < NS; i++){
        if (CVT != 0) { CP_WAIT1(); } else { CP_WAIT2(); }
        __syncthreads();
        issue(i + 3);
        CP_COMMIT();

        const uint32_t Ab = (CVT == 1) ? (CVBO + (uint32_t)(i & 1) * 16384u)
                                       : ((uint32_t)(i & 3) * PSTG);
        const uint32_t Bb = (CVT == 2) ? (CVBO + (uint32_t)(i & 1) * 16384u)
                                       : ((uint32_t)(i & 3) * PSTG + (CVT == 0 ? 16384u : 0u));
        #pragma unroll
        for (int ks = 0; ks < 2; ks++){
            uint32_t Afh[4][4], Afl[4][4], Bfh[2][4], Bfl[2][4];
            const uint32_t qa = ((aC0 + 2 * ks) ^ lqA) * 16u;
            const uint32_t qb = ((bC0 + 2 * ks) ^ lqB) * 16u;
            #pragma unroll
            for (int mi = 0; mi < 4; mi++){
                uint32_t ad = sbase + Ab + (uint32_t)(aRow + mi * 16) * 64u + qa;
                LDSM4(Afh[mi], ad);
                LDSM4(Afl[mi], ad + 8192);
            }
            #pragma unroll
            for (int nb = 0; nb < 2; nb++){
                uint32_t bd = sbase + Bb + (uint32_t)(bRow + nb * 16) * 64u + qb;
                LDSM4(Bfh[nb], bd);
                LDSM4(Bfl[nb], bd + 8192);
            }
            if (ks == 0) convert(i + 1);   // overlap conversion with MMA block
            // pass 1: Ah*Bh
            #pragma unroll
            for (int mi = 0; mi < 4; mi++)
                #pragma unroll
                for (int ni = 0; ni < 4; ni++){
                    int nb = ni >> 1, h = (ni & 1) * 2;
                    MMA16816(acc[mi][ni], Afh[mi], Bfh[nb][h], Bfh[nb][h + 1]);
                }
            // pass 2: Ah*Bl
            #pragma unroll
            for (int mi = 0; mi < 4; mi++)
                #pragma unroll
                for (int ni = 0; ni < 4; ni++){
                    int nb = ni >> 1, h = (ni & 1) * 2;
                    MMA16816(acc[mi][ni], Afh[mi], Bfl[nb][h], Bfl[nb][h + 1]);
                }
            // pass 3: Al*Bh
            #pragma unroll
            for (int mi = 0; mi < 4; mi++)
                #pragma unroll
                for (int ni = 0; ni < 4; ni++){
                    int nb = ni >> 1, h = (ni & 1) * 2;
                    MMA16816(acc[mi][ni], Afl[mi], Bfh[nb][h], Bfh[nb][h + 1]);
                }
        }
    }

    // ---- epilogue
    const int r1 = lane >> 2, cq = (lane & 3) * 2;
    if (EPI == 3){
        __nv_bfloat16* Ch = (__nv_bfloat16*)a.C;
        __nv_bfloat16* Cl = (__nv_bfloat16*)a.C2;
        const long cb = (long)b * a.sC;
        #pragma unroll
        for (int mi = 0; mi < 4; mi++){
            int m0 = bm0 + wm * 64 + mi * 16 + r1;
            #pragma unroll
            for (int ni = 0; ni < 4; ni++){
                int n = bn0 + wn * 32 + ni * 8 + cq;
                float v0 = acc[mi][ni][0], v1 = acc[mi][ni][1];
                float v2 = acc[mi][ni][2], v3 = acc[mi][ni][3];
                *(uint32_t*)(Ch + cb + (long)m0 * a.ldc + n)       = pack_hi(v0, v1);
                *(uint32_t*)(Cl + cb + (long)m0 * a.ldc + n)       = pack_lo(v0, v1);
                *(uint32_t*)(Ch + cb + (long)(m0 + 8) * a.ldc + n) = pack_hi(v2, v3);
                *(uint32_t*)(Cl + cb + (long)(m0 + 8) * a.ldc + n) = pack_lo(v2, v3);
            }
        }
    } else {
        float* Cb = (float*)a.C + (long)b * a.sC;
        #pragma unroll
        for (int mi = 0; mi < 4; mi++){
            int m0 = bm0 + wm * 64 + mi * 16 + r1;
            float s0 = 0.f, b0_ = 0.f, s1 = 0.f, b1_ = 0.f;
            if (EPI == 1){
                s0 = a.gs[m0] * BN_RS;     b0_ = a.bs[m0];
                s1 = a.gs[m0 + 8] * BN_RS; b1_ = a.bs[m0 + 8];
            }
            #pragma unroll
            for (int ni = 0; ni < 4; ni++){
                int n = bn0 + wn * 32 + ni * 8 + cq;
                float v0 = acc[mi][ni][0], v1 = acc[mi][ni][1];
                float v2 = acc[mi][ni][2], v3 = acc[mi][ni][3];
                if (EPI == 1){
                    v0 = fmaxf(fmaf(v0, s0, b0_), 0.f); v1 = fmaxf(fmaf(v1, s0, b0_), 0.f);
                    v2 = fmaxf(fmaf(v2, s1, b1_), 0.f); v3 = fmaxf(fmaf(v3, s1, b1_), 0.f);
                } else if (EPI == 2){
                    float gs0 = a.gs[n] * BN_RS, bb0 = a.bs[n];
                    float gs1 = a.gs[n + 1] * BN_RS, bb1 = a.bs[n + 1];
                    v0 = fmaxf(fmaf(v0, gs0, bb0), 0.f); v1 = fmaxf(fmaf(v1, gs1, bb1), 0.f);
                    v2 = fmaxf(fmaf(v2, gs0, bb0), 0.f); v3 = fmaxf(fmaf(v3, gs1, bb1), 0.f);
                }
                *(float2*)(Cb + (long)m0 * a.ldc + n)       = make_float2(v0, v1);
                *(float2*)(Cb + (long)(m0 + 8) * a.ldc + n) = make_float2(v2, v3);
            }
        }
    }
}

#define SMEM_STD 131072   // 4 x 32KB (two pre-split operands)
#define SMEM_CVT 163840   // 4x16KB pre-split + 4x16KB fp32 + 2x16KB dbuf

// ---------------- reductions ----------------
__device__ __forceinline__ float warpSum(float v){
    #pragma unroll
    for (int o = 16; o; o >>= 1) v += __shfl_xor_sync(0xffffffffu, v, o);
    return v;
}
__device__ __forceinline__ float warpMax(float v){
    #pragma unroll
    for (int o = 16; o; o >>= 1) v = fmaxf(v, __shfl_xor_sync(0xffffffffu, v, o));
    return v;
}
__device__ __forceinline__ float blockSum(float v){
    __shared__ float sh[32];
    int w = threadIdx.x >> 5, l = threadIdx.x & 31;
    v = warpSum(v);
    if (l == 0) sh[w] = v;
    __syncthreads();
    int nw = blockDim.x >> 5;
    if (w == 0){ float x = (l < nw) ? sh[l] : 0.0f; x = warpSum(x); if (l == 0) sh[0] = x; }
    __syncthreads();
    float r = sh[0];
    __syncthreads();
    return r;
}
__device__ __forceinline__ float blockMax(float v){
    __shared__ float sh[32];
    int w = threadIdx.x >> 5, l = threadIdx.x & 31;
    v = warpMax(v);
    if (l == 0) sh[w] = v;
    __syncthreads();
    int nw = blockDim.x >> 5;
    if (w == 0){ float x = (l < nw) ? sh[l] : -INFINITY; x = warpMax(x); if (l == 0) sh[0] = x; }
    __syncthreads();
    float r = sh[0];
    __syncthreads();
    return r;
}

// ---------------- elementwise kernels ----------------
__global__ void __launch_bounds__(256)
k_split(const float4* __restrict__ in, uint2* __restrict__ hi, uint2* __restrict__ lo, int n4)
{
    int i = blockIdx.x * blockDim.x + threadIdx.x;
    int stride = gridDim.x * blockDim.x;
    for (; i < n4; i += stride){
        float4 v = in[i];
        uint2 h, l;
        split16(v, h, l);
        hi[i] = h;
        lo[i] = l;
    }
}

// normalize Yv rows over C=2048, deinterleave even/odd channels, write split bf16
__global__ void __launch_bounds__(256)
k_norm_v2l(const float4* __restrict__ Y,
           uint32_t* __restrict__ Eh, uint32_t* __restrict__ El,
           uint32_t* __restrict__ Oh, uint32_t* __restrict__ Ol)
{
    long row = blockIdx.x;
    const float4* y = Y + row * 512;
    int t = threadIdx.x;
    float4 v0 = y[t], v1 = y[t + 256];
    float s = v0.x*v0.x + v0.y*v0.y + v0.z*v0.z + v0.w*v0.w
            + v1.x*v1.x + v1.y*v1.y + v1.z*v1.z + v1.w*v1.w;
    s = blockSum(s);
    float inv = 1.0f / fmaxf(sqrtf(s), 1e-12f);
    long eb = row * 512;
    Eh[eb + t] = pack_hi(v0.x * inv, v0.z * inv);
    El[eb + t] = pack_lo(v0.x * inv, v0.z * inv);
    Oh[eb + t] = pack_hi(v0.y * inv, v0.w * inv);
    Ol[eb + t] = pack_lo(v0.y * inv, v0.w * inv);
    Eh[eb + t + 256] = pack_hi(v1.x * inv, v1.z * inv);
    El[eb + t + 256] = pack_lo(v1.x * inv, v1.z * inv);
    Oh[eb + t + 256] = pack_hi(v1.y * inv, v1.w * inv);
    Ol[eb + t + 256] = pack_lo(v1.y * inv, v1.w * inv);
}

// normalize Zl rows over D=256, write split bf16
__global__ void __launch_bounds__(128)
k_norm_rows(const float* __restrict__ Z, uint32_t* __restrict__ Zh, uint32_t* __restrict__ Zl)
{
    long row = blockIdx.x;
    const float2* z = (const float2*)(Z + row * 256);
    int t = threadIdx.x;
    float2 v = z[t];
    float s = blockSum(v.x * v.x + v.y * v.y);
    float inv = 1.0f / fmaxf(sqrtf(s), 1e-12f);
    Zh[row * 128 + t] = pack_hi(v.x * inv, v.y * inv);
    Zl[row * 128 + t] = pack_lo(v.x * inv, v.y * inv);
}

// transpose lat_hi/lo [b,256,1024] -> latT_hi/lo [b,1024,256]
__global__ void __launch_bounds__(256)
k_transpose(const uint32_t* __restrict__ sH, const uint32_t* __restrict__ sL,
            uint32_t* __restrict__ dH, uint32_t* __restrict__ dL)
{
    __shared__ unsigned short tile[32][34];
    const int b = blockIdx.z, h0 = blockIdx.x * 32, d0 = blockIdx.y * 32;
    const int t = threadIdx.x;
    const uint32_t* srcs[2] = {sH, sL};
    uint32_t* dsts[2] = {dH, dL};
    #pragma unroll
    for (int m = 0; m < 2; m++){
        #pragma unroll
        for (int i = 0; i < 2; i++){
            int s = t + i * 256;
            int d = s >> 4, hu = s & 15;
            uint32_t v = srcs[m][(long)(b * 256 + d0 + d) * 512 + (h0 >> 1) + hu];
            tile[d][2 * hu]     = (unsigned short)(v & 0xFFFFu);
            tile[d][2 * hu + 1] = (unsigned short)(v >> 16);
        }
        __syncthreads();
        #pragma unroll
        for (int i = 0; i < 2; i++){
            int s = t + i * 256;
            int h = s >> 4, du = s & 15;
            uint32_t v = (uint32_t)tile[2 * du][h] | ((uint32_t)tile[2 * du + 1][h] << 16);
            dsts[m][(long)(b * 1024 + h0 + h) * 128 + (d0 >> 1) + du] = v;
        }
        __syncthreads();
    }
}

// latent row inverse norms from hi/lo
__global__ void __launch_bounds__(256)
k_latnorm(const uint32_t* __restrict__ H, const uint32_t* __restrict__ L, float* __restrict__ R)
{
    long row = blockIdx.x;
    long base = row * 512;
    int t = threadIdx.x;
    float s = 0.0f;
    #pragma unroll
    for (int i = 0; i < 2; i++){
        long idx = base + t + i * 256;
        uint32_t uh = H[idx], ul = L[idx];
        float2 fh = __bfloat1622float2(*(__nv_bfloat162*)&uh);
        float2 fl = __bfloat1622float2(*(__nv_bfloat162*)&ul);
        float v0 = fh.x + fl.x, v1 = fh.y + fl.y;
        s += v0 * v0 + v1 * v1;
    }
    s = blockSum(s);
    if (t == 0) R[row] = 1.0f / fmaxf(sqrtf(s), 1e-12f);
}

// softmax over scaled gram rows; write split bf16
__global__ void __launch_bounds__(256)
k_softmax(const float* __restrict__ G, const float* __restrict__ R,
          uint32_t* __restrict__ Gh, uint32_t* __restrict__ Gl)
{
    long row = blockIdx.x;
    long bb = row >> 8;
    int t = threadIdx.x;
    float ri = R[row];
    float re = R[(bb << 8) + t];
    float x = G[row * 256 + t] * ri * re;
    float mx = blockMax(x);
    float p = expf(x - mx);
    float sm = blockSum(p);
    float g = p / sm;
    float gn = __shfl_down_sync(0xffffffffu, g, 1);
    if ((t & 1) == 0){
        Gh[row * 128 + (t >> 1)] = pack_hi(g, gn);
        Gl[row * 128 + (t >> 1)] = pack_lo(g, gn);
    }
}

// ---------------- launch ----------------
extern "C" void kernel_launch(void* const* d_in, const int* in_sizes, int n_in,
                              void* d_out, int out_size)
{
    const float* v2l = (const float*)d_in[0];
    const float* l2v = (const float*)d_in[1];
    const float* wv  = (const float*)d_in[2];
    const float* gv  = (const float*)d_in[3];
    const float* bv  = (const float*)d_in[4];
    const float* wl  = (const float*)d_in[5];
    const float* gl  = (const float*)d_in[6];
    const float* bl  = (const float*)d_in[7];
    float* out = (float*)d_out;

    float *Yv, *Zl, *G, *invr;
    __nv_bfloat16 *wvh, *wvl, *wlh, *wll;
    __nv_bfloat16 *Eh, *El, *Oh, *Ol, *Zh, *Zlo, *lath, *latl, *latTh, *latTl;
    __nv_bfloat16 *Ghb, *Glb, *l2Th, *l2Tl;
    cudaGetSymbolAddress((void**)&Yv, d_Yv);
    cudaGetSymbolAddress((void**)&Zl, d_Zl);
    cudaGetSymbolAddress((void**)&G, d_G);
    cudaGetSymbolAddress((void**)&invr, d_invr);
    cudaGetSymbolAddress((void**)&wvh, g_wvh);   cudaGetSymbolAddress((void**)&wvl, g_wvl);
    cudaGetSymbolAddress((void**)&wlh, g_wlh);   cudaGetSymbolAddress((void**)&wll, g_wll);
    cudaGetSymbolAddress((void**)&Eh, g_Eh);     cudaGetSymbolAddress((void**)&El, g_El);
    cudaGetSymbolAddress((void**)&Oh, g_Oh);     cudaGetSymbolAddress((void**)&Ol, g_Ol);
    cudaGetSymbolAddress((void**)&Zh, g_Zh);     cudaGetSymbolAddress((void**)&Zlo, g_Zlo);
    cudaGetSymbolAddress((void**)&lath, g_lath); cudaGetSymbolAddress((void**)&latl, g_latl);
    cudaGetSymbolAddress((void**)&latTh, g_latTh); cudaGetSymbolAddress((void**)&latTl, g_latTl);
    cudaGetSymbolAddress((void**)&Ghb, g_Gh);    cudaGetSymbolAddress((void**)&Glb, g_Gl);
    cudaGetSymbolAddress((void**)&l2Th, g_l2Th); cudaGetSymbolAddress((void**)&l2Tl, g_l2Tl);

    cudaFuncSetAttribute(mma_gemm<1,1,2>, cudaFuncAttributeMaxDynamicSharedMemorySize, SMEM_CVT);
    cudaFuncSetAttribute(mma_gemm<2,1,1>, cudaFuncAttributeMaxDynamicSharedMemorySize, SMEM_CVT);
    cudaFuncSetAttribute(mma_gemm<3,2,2>, cudaFuncAttributeMaxDynamicSharedMemorySize, SMEM_CVT);
    cudaFuncSetAttribute(mma_gemm<0,1,0>, cudaFuncAttributeMaxDynamicSharedMemorySize, SMEM_STD);
    cudaFuncSetAttribute(mma_gemm<3,1,0>, cudaFuncAttributeMaxDynamicSharedMemorySize, SMEM_STD);

    const long FEAT = (long)CCH * HWD;
    dim3 blk(256);

    // 0) split weights only (tiny)
    k_split<<<256, blk>>>((const float4*)wv, (uint2*)wvh, (uint2*)wvl, DD*HWD/4);
    k_split<<<256, blk>>>((const float4*)wl, (uint2*)wlh, (uint2*)wll, DD*HWD/4);

    // 1) Yv = relu(bn(Wv . V^T))  M=256 N=2048 K=1024; B = v2l fp32 (CVT=2)
    {
        GArgs a = { wvh, wvl, nullptr, nullptr, nullptr, nullptr, nullptr, nullptr,
                    v2l, nullptr,
                    Yv, nullptr, gv, bv, 0, FEAT, (long)DD*CCH, HWD, HWD, CCH, HWD };
        mma_gemm<1,1,2><<<dim3(CCH/128, DD/128, BATCH), blk, SMEM_CVT>>>(a);
    }
    // 2) Zl = relu(bn(Xl . Wl^T)) M=2048 N=256 K=1024; A = l2v fp32 (CVT=1)
    {
        GArgs a = { nullptr, nullptr, wlh, wll, nullptr, nullptr, nullptr, nullptr,
                    l2v, nullptr,
                    Zl, nullptr, gl, bl, FEAT, 0, (long)CCH*DD, HWD, HWD, DD, HWD };
        mma_gemm<2,1,1><<<dim3(DD/128, CCH/128, BATCH), blk, SMEM_CVT>>>(a);
    }
    // 3) norm Yv rows -> split E/O
    k_norm_v2l<<<BATCH*DD, blk>>>((const float4*)Yv,
        (uint32_t*)Eh, (uint32_t*)El, (uint32_t*)Oh, (uint32_t*)Ol);
    // 4) norm Zl rows -> split Zh/Zlo
    k_norm_rows<<<BATCH*CCH, 128>>>(Zl, (uint32_t*)Zh, (uint32_t*)Zlo);
    // 5) lat = E.Vlow^T + O.Vhigh^T  M=256 N=1024 K=1024x2; B = v2l fp32 (CVT=2)
    {
        GArgs a = { Eh, El, nullptr, nullptr, Oh, Ol, nullptr, nullptr,
                    v2l, v2l + (long)HWD*HWD,
                    lath, latl, nullptr, nullptr,
                    (long)DD*HWD, FEAT, (long)DD*HWD, HWD, HWD, HWD, HWD };
        mma_gemm<3,2,2><<<dim3(HWD/128, DD/128, BATCH), blk, SMEM_CVT>>>(a);
    }
    // 6) transpose lat -> latT
    k_transpose<<<dim3(32, 8, BATCH), blk>>>(
        (const uint32_t*)lath, (const uint32_t*)latl, (uint32_t*)latTh, (uint32_t*)latTl);
    // 7) latent row inverse norms
    k_latnorm<<<BATCH*DD, blk>>>((const uint32_t*)lath, (const uint32_t*)latl, invr);
    // 8) G = lat . lat^T  M=N=256 K=1024 (fp32 out)
    {
        GArgs a = { lath, latl, lath, latl, nullptr, nullptr, nullptr, nullptr,
                    nullptr, nullptr,
                    G, nullptr, nullptr, nullptr,
                    (long)DD*HWD, (long)DD*HWD, (long)DD*DD, HWD, HWD, DD, HWD };
        mma_gemm<0,1,0><<<dim3(DD/128, DD/128, BATCH), blk, SMEM_STD>>>(a);
    }
    // 9) aff = softmax(G * invr_d * invr_e) -> split bf16
    k_softmax<<<BATCH*DD, blk>>>(G, invr, (uint32_t*)Ghb, (uint32_t*)Glb);
    // 10) l2T = latT . aff^T  M=1024 N=256 K=256 -> split bf16
    {
        GArgs a = { latTh, latTl, Ghb, Glb, nullptr, nullptr, nullptr, nullptr,
                    nullptr, nullptr,
                    l2Th, l2Tl, nullptr, nullptr,
                    (long)HWD*DD, (long)DD*DD, (long)HWD*DD, DD, DD, DD, DD };
        mma_gemm<3,1,0><<<dim3(DD/128, HWD/128, BATCH), blk, SMEM_STD>>>(a);
    }
    // 11) out = Zl_adj . l2T^T  M=2048 N=1024 K=256 (fp32 out)
    {
        GArgs a = { Zh, Zlo, l2Th, l2Tl, nullptr, nullptr, nullptr, nullptr,
                    nullptr, nullptr,
                    out, nullptr, nullptr, nullptr,
                    (long)CCH*DD, (long)HWD*DD, (long)CCH*HWD, DD, DD, HWD, DD };
        mma_gemm<0,1,0><<<dim3(HWD/128, CCH/128, BATCH), blk, SMEM_STD>>>(a);
    }
}

// round 9
// speedup vs baseline: 1.1415x; 1.1415x over previous
#include <cuda_runtime.h>
#include <cuda_bf16.h>
#include <math.h>
#include <stdint.h>

#define BATCH 16
#define CCH   2048
#define HWD   1024
#define DD    256
#define BN_RS 0.9999950000374997f   // 1/sqrt(1 + 1e-5)

// ---------------- scratch (device globals; no allocation) ----------------
__device__ __align__(16) float d_Yv [BATCH * DD  * CCH];
__device__ __align__(16) float d_Zl [BATCH * CCH * DD ];
__device__ __align__(16) float d_G  [BATCH * DD  * DD ];
__device__ float d_invr[BATCH * DD];

// bf16 hi/lo split operand storage
__device__ __align__(16) __nv_bfloat16 g_v2lh[BATCH*CCH*HWD], g_v2ll[BATCH*CCH*HWD];
__device__ __align__(16) __nv_bfloat16 g_l2vh[BATCH*CCH*HWD], g_l2vl[BATCH*CCH*HWD];
__device__ __align__(16) __nv_bfloat16 g_wvh[DD*HWD], g_wvl[DD*HWD];
__device__ __align__(16) __nv_bfloat16 g_wlh[DD*HWD], g_wll[DD*HWD];
__device__ __align__(16) __nv_bfloat16 g_Eh[BATCH*DD*HWD], g_El[BATCH*DD*HWD];
__device__ __align__(16) __nv_bfloat16 g_Oh[BATCH*DD*HWD], g_Ol[BATCH*DD*HWD];
__device__ __align__(16) __nv_bfloat16 g_Zh[BATCH*CCH*DD], g_Zlo[BATCH*CCH*DD];
__device__ __align__(16) __nv_bfloat16 g_lath[BATCH*DD*HWD], g_latl[BATCH*DD*HWD];
__device__ __align__(16) __nv_bfloat16 g_latTh[BATCH*HWD*DD], g_latTl[BATCH*HWD*DD];
__device__ __align__(16) __nv_bfloat16 g_Gh[BATCH*DD*DD], g_Gl[BATCH*DD*DD];
__device__ __align__(16) __nv_bfloat16 g_l2Th[BATCH*HWD*DD], g_l2Tl[BATCH*HWD*DD];

// ---------------- helpers ----------------
__device__ __forceinline__ uint32_t cvta_s(const void* p){
    return (uint32_t)__cvta_generic_to_shared(p);
}
__device__ __forceinline__ void cpa16(uint32_t d, const void* s){
    asm volatile("cp.async.cg.shared.global [%0], [%1], 16;" :: "r"(d), "l"(s));
}
#define CP_COMMIT() asm volatile("cp.async.commit_group;")
#define CP_WAIT1()  asm volatile("cp.async.wait_group 1;")

#define LDSM4(R, addr) \
    asm volatile("ldmatrix.sync.aligned.m8n8.x4.shared.b16 {%0,%1,%2,%3}, [%4];" \
        : "=r"((R)[0]), "=r"((R)[1]), "=r"((R)[2]), "=r"((R)[3]) : "r"(addr))

#define MMA16816(d, A, b0, b1) \
    asm volatile("mma.sync.aligned.m16n8k16.row.col.f32.bf16.bf16.f32 " \
        "{%0,%1,%2,%3}, {%4,%5,%6,%7}, {%8,%9}, {%0,%1,%2,%3};" \
        : "+f"((d)[0]), "+f"((d)[1]), "+f"((d)[2]), "+f"((d)[3]) \
        : "r"((A)[0]), "r"((A)[1]), "r"((A)[2]), "r"((A)[3]), "r"(b0), "r"(b1))

__device__ __forceinline__ void split16(float4 v, uint2& hi, uint2& lo){
    uint32_t ux = __float_as_uint(v.x), uy = __float_as_uint(v.y);
    uint32_t uz = __float_as_uint(v.z), uw = __float_as_uint(v.w);
    hi.x = __byte_perm(ux, uy, 0x7632);
    hi.y = __byte_perm(uz, uw, 0x7632);
    float lx = v.x - __uint_as_float(ux & 0xFFFF0000u);
    float ly = v.y - __uint_as_float(uy & 0xFFFF0000u);
    float lz = v.z - __uint_as_float(uz & 0xFFFF0000u);
    float lw = v.w - __uint_as_float(uw & 0xFFFF0000u);
    __nv_bfloat162 l01 = __floats2bfloat162_rn(lx, ly);
    __nv_bfloat162 l23 = __floats2bfloat162_rn(lz, lw);
    lo.x = *(uint32_t*)&l01;
    lo.y = *(uint32_t*)&l23;
}
__device__ __forceinline__ uint32_t pack_hi(float x, float y){
    return __byte_perm(__float_as_uint(x), __float_as_uint(y), 0x7632);
}
__device__ __forceinline__ uint32_t pack_lo(float x, float y){
    float lx = x - __uint_as_float(__float_as_uint(x) & 0xFFFF0000u);
    float ly = y - __uint_as_float(__float_as_uint(y) & 0xFFFF0000u);
    __nv_bfloat162 p = __floats2bfloat162_rn(lx, ly);
    return *(uint32_t*)&p;
}

// ---------------- bf16 hi/lo NT GEMM, cp.async pipelined, 2 CTA/SM --------
// D[m,n] = sum_p sum_k A_p[m,k]*B_p[n,k], 3 bf16 passes (hh + hl + lh)
struct GArgs {
    const __nv_bfloat16 *A0h, *A0l, *B0h, *B0l;
    const __nv_bfloat16 *A1h, *A1l, *B1h, *B1l;
    void *C, *C2;                   // EPI 0/1/2: C=float*; EPI 3: C=hi bf16*, C2=lo bf16*
    const float *gs, *bs;
    long sA, sB, sC;
    int lda, ldb, ldc, K;
};

// 3-stage ring, stage = 32KB: Ah@0, Al@8K, Bh@16K, Bl@24K. Rows 64B,
// swizzle quarter q = ch ^ ((row>>1)&3).
#define STG3   32768
#define G_SMEM (3 * STG3)

template<int EPI, int NP>
__global__ void __launch_bounds__(256, 2) mma_gemm(GArgs a)
{
    extern __shared__ __align__(128) char smem[];
    const int tid = threadIdx.x, w = tid >> 5, lane = tid & 31;
    const int bn0 = blockIdx.x << 7, bm0 = blockIdx.y << 7, b = blockIdx.z;
    const int KS = a.K >> 5;
    const int NS = KS * NP;
    const uint32_t sbase = cvta_s(smem);
    const int wm = w >> 2, wn = w & 3;

    const int r0 = tid >> 2, ch = tid & 3;
    const uint32_t q16 = (uint32_t)((ch ^ ((r0 >> 1) & 3)) * 16);

    auto issue = [&](int s){
        if (s >= NS) return;
        int p = (NP == 2 && s >= KS) ? 1 : 0;
        long k0 = (long)(s - p * KS) * 32;
        const __nv_bfloat16* srcs[4] = {
            (p ? a.A1h : a.A0h) + (long)b * a.sA + (long)bm0 * a.lda + k0,
            (p ? a.A1l : a.A0l) + (long)b * a.sA + (long)bm0 * a.lda + k0,
            (p ? a.B1h : a.B0h) + (long)b * a.sB + (long)bn0 * a.ldb + k0,
            (p ? a.B1l : a.B0l) + (long)b * a.sB + (long)bn0 * a.ldb + k0
        };
        uint32_t dst0 = sbase + (uint32_t)(s % 3) * STG3 + (uint32_t)r0 * 64u + q16;
        #pragma unroll
        for (int sub = 0; sub < 4; sub++){
            long ld = (sub < 2) ? a.lda : a.ldb;
            const __nv_bfloat16* sp = srcs[sub] + (long)r0 * ld + ch * 8;
            cpa16(dst0 + sub * 8192,        sp);
            cpa16(dst0 + sub * 8192 + 4096, sp + 64 * ld);
        }
    };

    float acc[4][4][4];
    #pragma unroll
    for (int i = 0; i < 4; i++)
        #pragma unroll
        for (int j = 0; j < 4; j++)
            #pragma unroll
            for (int t = 0; t < 4; t++) acc[i][j][t] = 0.0f;

    // ldmatrix addressing
    const int aRow = wm * 64 + (lane & 15);
    const uint32_t lqA = (uint32_t)(((lane & 15) >> 1) & 3);
    const uint32_t aC0 = (uint32_t)(lane >> 4);
    const int bRow = wn * 32 + (lane & 7) + ((lane >> 4) & 1) * 8;
    const uint32_t lqB = (uint32_t)(((lane & 7) >> 1) & 3);
    const uint32_t bC0 = (uint32_t)((lane >> 3) & 1);

    // prologue: 2 stages in flight
    issue(0); CP_COMMIT();
    issue(1); CP_COMMIT();

    for (int i = 0; i < NS; i++){
        CP_WAIT1();
        __syncthreads();
        issue(i + 2);        // overwrites buffer (i+2)%3 == (i-1)%3, free since all
        CP_COMMIT();         // warps passed compute of iter i-1 at the barrier above

        const uint32_t stb = sbase + (uint32_t)(i % 3) * STG3;
        #pragma unroll
        for (int ks = 0; ks < 2; ks++){
            const uint32_t qa = ((aC0 + 2 * ks) ^ lqA) * 16u;
            const uint32_t qb = ((bC0 + 2 * ks) ^ lqB) * 16u;
            uint32_t Afh[4][4], Bfh[2][4], Bfl[2][4];
            #pragma unroll
            for (int mi = 0; mi < 4; mi++){
                uint32_t ad = stb + (uint32_t)(aRow + mi * 16) * 64u + qa;
                LDSM4(Afh[mi], ad);
            }
            #pragma unroll
            for (int nb = 0; nb < 2; nb++){
                uint32_t bd = stb + 16384u + (uint32_t)(bRow + nb * 16) * 64u + qb;
                LDSM4(Bfh[nb], bd);
                LDSM4(Bfl[nb], bd + 8192);
            }
            // pass 1: Ah*Bh
            #pragma unroll
            for (int mi = 0; mi < 4; mi++)
                #pragma unroll
                for (int ni = 0; ni < 4; ni++){
                    int nb = ni >> 1, h = (ni & 1) * 2;
                    MMA16816(acc[mi][ni], Afh[mi], Bfh[nb][h], Bfh[nb][h + 1]);
                }
            // pass 2: Ah*Bl
            #pragma unroll
            for (int mi = 0; mi < 4; mi++)
                #pragma unroll
                for (int ni = 0; ni < 4; ni++){
                    int nb = ni >> 1, h = (ni & 1) * 2;
                    MMA16816(acc[mi][ni], Afh[mi], Bfl[nb][h], Bfl[nb][h + 1]);
                }
            // deferred Al loads (keeps peak live regs under the 128 cap)
            uint32_t Afl[4][4];
            #pragma unroll
            for (int mi = 0; mi < 4; mi++){
                uint32_t ad = stb + 8192u + (uint32_t)(aRow + mi * 16) * 64u + qa;
                LDSM4(Afl[mi], ad);
            }
            // pass 3: Al*Bh
            #pragma unroll
            for (int mi = 0; mi < 4; mi++)
                #pragma unroll
                for (int ni = 0; ni < 4; ni++){
                    int nb = ni >> 1, h = (ni & 1) * 2;
                    MMA16816(acc[mi][ni], Afl[mi], Bfh[nb][h], Bfh[nb][h + 1]);
                }
        }
    }

    // ---- epilogue
    const int r1 = lane >> 2, cq = (lane & 3) * 2;
    if (EPI == 3){
        __nv_bfloat16* Ch = (__nv_bfloat16*)a.C;
        __nv_bfloat16* Cl = (__nv_bfloat16*)a.C2;
        const long cb = (long)b * a.sC;
        #pragma unroll
        for (int mi = 0; mi < 4; mi++){
            int m0 = bm0 + wm * 64 + mi * 16 + r1;
            #pragma unroll
            for (int ni = 0; ni < 4; ni++){
                int n = bn0 + wn * 32 + ni * 8 + cq;
                float v0 = acc[mi][ni][0], v1 = acc[mi][ni][1];
                float v2 = acc[mi][ni][2], v3 = acc[mi][ni][3];
                *(uint32_t*)(Ch + cb + (long)m0 * a.ldc + n)       = pack_hi(v0, v1);
                *(uint32_t*)(Cl + cb + (long)m0 * a.ldc + n)       = pack_lo(v0, v1);
                *(uint32_t*)(Ch + cb + (long)(m0 + 8) * a.ldc + n) = pack_hi(v2, v3);
                *(uint32_t*)(Cl + cb + (long)(m0 + 8) * a.ldc + n) = pack_lo(v2, v3);
            }
        }
    } else {
        float* Cb = (float*)a.C + (long)b * a.sC;
        #pragma unroll
        for (int mi = 0; mi < 4; mi++){
            int m0 = bm0 + wm * 64 + mi * 16 + r1;
            float s0 = 0.f, b0_ = 0.f, s1 = 0.f, b1_ = 0.f;
            if (EPI == 1){
                s0 = a.gs[m0] * BN_RS;     b0_ = a.bs[m0];
                s1 = a.gs[m0 + 8] * BN_RS; b1_ = a.bs[m0 + 8];
            }
            #pragma unroll
            for (int ni = 0; ni < 4; ni++){
                int n = bn0 + wn * 32 + ni * 8 + cq;
                float v0 = acc[mi][ni][0], v1 = acc[mi][ni][1];
                float v2 = acc[mi][ni][2], v3 = acc[mi][ni][3];
                if (EPI == 1){
                    v0 = fmaxf(fmaf(v0, s0, b0_), 0.f); v1 = fmaxf(fmaf(v1, s0, b0_), 0.f);
                    v2 = fmaxf(fmaf(v2, s1, b1_), 0.f); v3 = fmaxf(fmaf(v3, s1, b1_), 0.f);
                } else if (EPI == 2){
                    float gs0 = a.gs[n] * BN_RS, bb0 = a.bs[n];
                    float gs1 = a.gs[n + 1] * BN_RS, bb1 = a.bs[n + 1];
                    v0 = fmaxf(fmaf(v0, gs0, bb0), 0.f); v1 = fmaxf(fmaf(v1, gs1, bb1), 0.f);
                    v2 = fmaxf(fmaf(v2, gs0, bb0), 0.f); v3 = fmaxf(fmaf(v3, gs1, bb1), 0.f);
                }
                *(float2*)(Cb + (long)m0 * a.ldc + n)       = make_float2(v0, v1);
                *(float2*)(Cb + (long)(m0 + 8) * a.ldc + n) = make_float2(v2, v3);
            }
        }
    }
}

// ---------------- reductions ----------------
__device__ __forceinline__ float warpSum(float v){
    #pragma unroll
    for (int o = 16; o; o >>= 1) v += __shfl_xor_sync(0xffffffffu, v, o);
    return v;
}
__device__ __forceinline__ float warpMax(float v){
    #pragma unroll
    for (int o = 16; o; o >>= 1) v = fmaxf(v, __shfl_xor_sync(0xffffffffu, v, o));
    return v;
}
__device__ __forceinline__ float blockSum(float v){
    __shared__ float sh[32];
    int w = threadIdx.x >> 5, l = threadIdx.x & 31;
    v = warpSum(v);
    if (l == 0) sh[w] = v;
    __syncthreads();
    int nw = blockDim.x >> 5;
    if (w == 0){ float x = (l < nw) ? sh[l] : 0.0f; x = warpSum(x); if (l == 0) sh[0] = x; }
    __syncthreads();
    float r = sh[0];
    __syncthreads();
    return r;
}
__device__ __forceinline__ float blockMax(float v){
    __shared__ float sh[32];
    int w = threadIdx.x >> 5, l = threadIdx.x & 31;
    v = warpMax(v);
    if (l == 0) sh[w] = v;
    __syncthreads();
    int nw = blockDim.x >> 5;
    if (w == 0){ float x = (l < nw) ? sh[l] : -INFINITY; x = warpMax(x); if (l == 0) sh[0] = x; }
    __syncthreads();
    float r = sh[0];
    __syncthreads();
    return r;
}

// ---------------- elementwise kernels ----------------
__global__ void __launch_bounds__(256)
k_split(const float4* __restrict__ in, uint2* __restrict__ hi, uint2* __restrict__ lo, int n4)
{
    int i = blockIdx.x * blockDim.x + threadIdx.x;
    int stride = gridDim.x * blockDim.x;
    for (; i < n4; i += stride){
        float4 v = in[i];
        uint2 h, l;
        split16(v, h, l);
        hi[i] = h;
        lo[i] = l;
    }
}

__global__ void __launch_bounds__(256)
k_norm_v2l(const float4* __restrict__ Y,
           uint32_t* __restrict__ Eh, uint32_t* __restrict__ El,
           uint32_t* __restrict__ Oh, uint32_t* __restrict__ Ol)
{
    long row = blockIdx.x;
    const float4* y = Y + row * 512;
    int t = threadIdx.x;
    float4 v0 = y[t], v1 = y[t + 256];
    float s = v0.x*v0.x + v0.y*v0.y + v0.z*v0.z + v0.w*v0.w
            + v1.x*v1.x + v1.y*v1.y + v1.z*v1.z + v1.w*v1.w;
    s = blockSum(s);
    float inv = 1.0f / fmaxf(sqrtf(s), 1e-12f);
    long eb = row * 512;
    Eh[eb + t] = pack_hi(v0.x * inv, v0.z * inv);
    El[eb + t] = pack_lo(v0.x * inv, v0.z * inv);
    Oh[eb + t] = pack_hi(v0.y * inv, v0.w * inv);
    Ol[eb + t] = pack_lo(v0.y * inv, v0.w * inv);
    Eh[eb + t + 256] = pack_hi(v1.x * inv, v1.z * inv);
    El[eb + t + 256] = pack_lo(v1.x * inv, v1.z * inv);
    Oh[eb + t + 256] = pack_hi(v1.y * inv, v1.w * inv);
    Ol[eb + t + 256] = pack_lo(v1.y * inv, v1.w * inv);
}

__global__ void __launch_bounds__(128)
k_norm_rows(const float* __restrict__ Z, uint32_t* __restrict__ Zh, uint32_t* __restrict__ Zl)
{
    long row = blockIdx.x;
    const float2* z = (const float2*)(Z + row * 256);
    int t = threadIdx.x;
    float2 v = z[t];
    float s = blockSum(v.x * v.x + v.y * v.y);
    float inv = 1.0f / fmaxf(sqrtf(s), 1e-12f);
    Zh[row * 128 + t] = pack_hi(v.x * inv, v.y * inv);
    Zl[row * 128 + t] = pack_lo(v.x * inv, v.y * inv);
}

__global__ void __launch_bounds__(256)
k_transpose(const uint32_t* __restrict__ sH, const uint32_t* __restrict__ sL,
            uint32_t* __restrict__ dH, uint32_t* __restrict__ dL)
{
    __shared__ unsigned short tile[32][34];
    const int b = blockIdx.z, h0 = blockIdx.x * 32, d0 = blockIdx.y * 32;
    const int t = threadIdx.x;
    const uint32_t* srcs[2] = {sH, sL};
    uint32_t* dsts[2] = {dH, dL};
    #pragma unroll
    for (int m = 0; m < 2; m++){
        #pragma unroll
        for (int i = 0; i < 2; i++){
            int s = t + i * 256;
            int d = s >> 4, hu = s & 15;
            uint32_t v = srcs[m][(long)(b * 256 + d0 + d) * 512 + (h0 >> 1) + hu];
            tile[d][2 * hu]     = (unsigned short)(v & 0xFFFFu);
            tile[d][2 * hu + 1] = (unsigned short)(v >> 16);
        }
        __syncthreads();
        #pragma unroll
        for (int i = 0; i < 2; i++){
            int s = t + i * 256;
            int h = s >> 4, du = s & 15;
            uint32_t v = (uint32_t)tile[2 * du][h] | ((uint32_t)tile[2 * du + 1][h] << 16);
            dsts[m][(long)(b * 1024 + h0 + h) * 128 + (d0 >> 1) + du] = v;
        }
        __syncthreads();
    }
}

__global__ void __launch_bounds__(256)
k_latnorm(const uint32_t* __restrict__ H, const uint32_t* __restrict__ L, float* __restrict__ R)
{
    long row = blockIdx.x;
    long base = row * 512;
    int t = threadIdx.x;
    float s = 0.0f;
    #pragma unroll
    for (int i = 0; i < 2; i++){
        long idx = base + t + i * 256;
        uint32_t uh = H[idx], ul = L[idx];
        float2 fh = __bfloat1622float2(*(__nv_bfloat162*)&uh);
        float2 fl = __bfloat1622float2(*(__nv_bfloat162*)&ul);
        float v0 = fh.x + fl.x, v1 = fh.y + fl.y;
        s += v0 * v0 + v1 * v1;
    }
    s = blockSum(s);
    if (t == 0) R[row] = 1.0f / fmaxf(sqrtf(s), 1e-12f);
}

__global__ void __launch_bounds__(256)
k_softmax(const float* __restrict__ G, const float* __restrict__ R,
          uint32_t* __restrict__ Gh, uint32_t* __restrict__ Gl)
{
    long row = blockIdx.x;
    long bb = row >> 8;
    int t = threadIdx.x;
    float ri = R[row];
    float re = R[(bb << 8) + t];
    float x = G[row * 256 + t] * ri * re;
    float mx = blockMax(x);
    float p = expf(x - mx);
    float sm = blockSum(p);
    float g = p / sm;
    float gn = __shfl_down_sync(0xffffffffu, g, 1);
    if ((t & 1) == 0){
        Gh[row * 128 + (t >> 1)] = pack_hi(g, gn);
        Gl[row * 128 + (t >> 1)] = pack_lo(g, gn);
    }
}

// ---------------- launch ----------------
extern "C" void kernel_launch(void* const* d_in, const int* in_sizes, int n_in,
                              void* d_out, int out_size)
{
    const float* v2l = (const float*)d_in[0];
    const float* l2v = (const float*)d_in[1];
    const float* wv  = (const float*)d_in[2];
    const float* gv  = (const float*)d_in[3];
    const float* bv  = (const float*)d_in[4];
    const float* wl  = (const float*)d_in[5];
    const float* gl  = (const float*)d_in[6];
    const float* bl  = (const float*)d_in[7];
    float* out = (float*)d_out;

    float *Yv, *Zl, *G, *invr;
    __nv_bfloat16 *v2lh, *v2ll, *l2vh, *l2vl, *wvh, *wvl, *wlh, *wll;
    __nv_bfloat16 *Eh, *El, *Oh, *Ol, *Zh, *Zlo, *lath, *latl, *latTh, *latTl;
    __nv_bfloat16 *Ghb, *Glb, *l2Th, *l2Tl;
    cudaGetSymbolAddress((void**)&Yv, d_Yv);
    cudaGetSymbolAddress((void**)&Zl, d_Zl);
    cudaGetSymbolAddress((void**)&G, d_G);
    cudaGetSymbolAddress((void**)&invr, d_invr);
    cudaGetSymbolAddress((void**)&v2lh, g_v2lh); cudaGetSymbolAddress((void**)&v2ll, g_v2ll);
    cudaGetSymbolAddress((void**)&l2vh, g_l2vh); cudaGetSymbolAddress((void**)&l2vl, g_l2vl);
    cudaGetSymbolAddress((void**)&wvh, g_wvh);   cudaGetSymbolAddress((void**)&wvl, g_wvl);
    cudaGetSymbolAddress((void**)&wlh, g_wlh);   cudaGetSymbolAddress((void**)&wll, g_wll);
    cudaGetSymbolAddress((void**)&Eh, g_Eh);     cudaGetSymbolAddress((void**)&El, g_El);
    cudaGetSymbolAddress((void**)&Oh, g_Oh);     cudaGetSymbolAddress((void**)&Ol, g_Ol);
    cudaGetSymbolAddress((void**)&Zh, g_Zh);     cudaGetSymbolAddress((void**)&Zlo, g_Zlo);
    cudaGetSymbolAddress((void**)&lath, g_lath); cudaGetSymbolAddress((void**)&latl, g_latl);
    cudaGetSymbolAddress((void**)&latTh, g_latTh); cudaGetSymbolAddress((void**)&latTl, g_latTl);
    cudaGetSymbolAddress((void**)&Ghb, g_Gh);    cudaGetSymbolAddress((void**)&Glb, g_Gl);
    cudaGetSymbolAddress((void**)&l2Th, g_l2Th); cudaGetSymbolAddress((void**)&l2Tl, g_l2Tl);

    cudaFuncSetAttribute(mma_gemm<0,1>, cudaFuncAttributeMaxDynamicSharedMemorySize, G_SMEM);
    cudaFuncSetAttribute(mma_gemm<0,2>, cudaFuncAttributeMaxDynamicSharedMemorySize, G_SMEM);
    cudaFuncSetAttribute(mma_gemm<1,1>, cudaFuncAttributeMaxDynamicSharedMemorySize, G_SMEM);
    cudaFuncSetAttribute(mma_gemm<2,1>, cudaFuncAttributeMaxDynamicSharedMemorySize, G_SMEM);
    cudaFuncSetAttribute(mma_gemm<3,1>, cudaFuncAttributeMaxDynamicSharedMemorySize, G_SMEM);
    cudaFuncSetAttribute(mma_gemm<3,2>, cudaFuncAttributeMaxDynamicSharedMemorySize, G_SMEM);

    const long FEAT = (long)CCH * HWD;
    dim3 blk(256);

    // 0) splits of raw inputs + weights
    k_split<<<8192, blk>>>((const float4*)v2l, (uint2*)v2lh, (uint2*)v2ll, (int)(BATCH*FEAT/4));
    k_split<<<8192, blk>>>((const float4*)l2v, (uint2*)l2vh, (uint2*)l2vl, (int)(BATCH*FEAT/4));
    k_split<<<256, blk>>>((const float4*)wv, (uint2*)wvh, (uint2*)wvl, DD*HWD/4);
    k_split<<<256, blk>>>((const float4*)wl, (uint2*)wlh, (uint2*)wll, DD*HWD/4);

    // 1) Yv = relu(bn(Wv . V^T))  M=256 N=2048 K=1024
    {
        GArgs a = { wvh, wvl, v2lh, v2ll, nullptr, nullptr, nullptr, nullptr,
                    Yv, nullptr, gv, bv, 0, FEAT, (long)DD*CCH, HWD, HWD, CCH, HWD };
        mma_gemm<1,1><<<dim3(CCH/128, DD/128, BATCH), blk, G_SMEM>>>(a);
    }
    // 2) Zl = relu(bn(Xl . Wl^T)) M=2048 N=256 K=1024
    {
        GArgs a = { l2vh, l2vl, wlh, wll, nullptr, nullptr, nullptr, nullptr,
                    Zl, nullptr, gl, bl, FEAT, 0, (long)CCH*DD, HWD, HWD, DD, HWD };
        mma_gemm<2,1><<<dim3(DD/128, CCH/128, BATCH), blk, G_SMEM>>>(a);
    }
    // 3) norm Yv rows -> split E/O
    k_norm_v2l<<<BATCH*DD, blk>>>((const float4*)Yv,
        (uint32_t*)Eh, (uint32_t*)El, (uint32_t*)Oh, (uint32_t*)Ol);
    // 4) norm Zl rows -> split Zh/Zlo
    k_norm_rows<<<BATCH*CCH, 128>>>(Zl, (uint32_t*)Zh, (uint32_t*)Zlo);
    // 5) lat = E.Vlow^T + O.Vhigh^T  M=256 N=1024 K=1024x2 -> split bf16 out
    {
        GArgs a = { Eh, El, v2lh, v2ll, Oh, Ol, v2lh + (long)HWD*HWD, v2ll + (long)HWD*HWD,
                    lath, latl, nullptr, nullptr,
                    (long)DD*HWD, FEAT, (long)DD*HWD, HWD, HWD, HWD, HWD };
        mma_gemm<3,2><<<dim3(HWD/128, DD/128, BATCH), blk, G_SMEM>>>(a);
    }
    // 6) transpose lat -> latT
    k_transpose<<<dim3(32, 8, BATCH), blk>>>(
        (const uint32_t*)lath, (const uint32_t*)latl, (uint32_t*)latTh, (uint32_t*)latTl);
    // 7) latent row inverse norms
    k_latnorm<<<BATCH*DD, blk>>>((const uint32_t*)lath, (const uint32_t*)latl, invr);
    // 8) G = lat . lat^T  M=N=256 K=1024 (fp32 out)
    {
        GArgs a = { lath, latl, lath, latl, nullptr, nullptr, nullptr, nullptr,
                    G, nullptr, nullptr, nullptr,
                    (long)DD*HWD, (long)DD*HWD, (long)DD*DD, HWD, HWD, DD, HWD };
        mma_gemm<0,1><<<dim3(DD/128, DD/128, BATCH), blk, G_SMEM>>>(a);
    }
    // 9) aff = softmax(G * invr_d * invr_e) -> split bf16
    k_softmax<<<BATCH*DD, blk>>>(G, invr, (uint32_t*)Ghb, (uint32_t*)Glb);
    // 10) l2T = latT . aff^T  M=1024 N=256 K=256 -> split bf16
    {
        GArgs a = { latTh, latTl, Ghb, Glb, nullptr, nullptr, nullptr, nullptr,
                    l2Th, l2Tl, nullptr, nullptr,
                    (long)HWD*DD, (long)DD*DD, (long)HWD*DD, DD, DD, DD, DD };
        mma_gemm<3,1><<<dim3(DD/128, HWD/128, BATCH), blk, G_SMEM>>>(a);
    }
    // 11) out = Zl_adj . l2T^T  M=2048 N=1024 K=256 (fp32 out)
    {
        GArgs a = { Zh, Zlo, l2Th, l2Tl, nullptr, nullptr, nullptr, nullptr,
                    out, nullptr, nullptr, nullptr,
                    (long)CCH*DD, (long)HWD*DD, (long)CCH*HWD, DD, DD, HWD, DD };
        mma_gemm<0,1><<<dim3(HWD/128, CCH/128, BATCH), blk, G_SMEM>>>(a);
    }
}